// round 15
// baseline (speedup 1.0000x reference)
#include <cuda_runtime.h>
#include <cuda_fp16.h>

#define DIM    256
#define LINE   24
#define HEADS  8
#define DHEAD  64
#define INNER  512
#define QKV    1536
#define NROWS  196608
#define NBLK   (NROWS / LINE)   // 8192

// ---------------------------------------------------------------------------
// Scratch (device globals, allocation-free)
// ---------------------------------------------------------------------------
__device__ __half g_xh   [(size_t)NROWS * DIM];    // 100 MB
__device__ __half g_qkvh [(size_t)NROWS * QKV];    // 604 MB  (q | k | v)
__device__ __half g_ih   [(size_t)NROWS * INNER];  // 201 MB
__device__ __half g_wqkvT[QKV * DIM];              // [n,k] K-major
__device__ __half g_woutT[DIM * INNER];            // [n,k] K-major

// ---------------------------------------------------------------------------
// Prep kernels
// ---------------------------------------------------------------------------
__global__ void __launch_bounds__(256) f2h_kernel(
    const float* __restrict__ in, __half* __restrict__ out, int n)
{
    int i = (blockIdx.x * 256 + threadIdx.x) * 4;
    if (i < n) {
        float4 v = *(const float4*)(in + i);
        *(__half2*)(out + i)     = __floats2half2_rn(v.x, v.y);
        *(__half2*)(out + i + 2) = __floats2half2_rn(v.z, v.w);
    }
}
__global__ void __launch_bounds__(256) prep_wqkv(
    const float* __restrict__ Wq, const float* __restrict__ Wkv,
    __half* __restrict__ wT)
{
    int idx = blockIdx.x * 256 + threadIdx.x;     // 1536*256
    int n = idx >> 8, k = idx & 255;
    float v = (n < 512) ? Wq[(size_t)k * 512 + n]
                        : Wkv[(size_t)k * 1024 + (n - 512)];
    wT[idx] = __float2half_rn(v);
}
__global__ void __launch_bounds__(256) prep_wout(
    const float* __restrict__ Wout, __half* __restrict__ wT)
{
    int idx = blockIdx.x * 256 + threadIdx.x;     // 256*512
    int n = idx >> 9, k = idx & 511;
    wT[idx] = __float2half_rn(Wout[(size_t)k * 256 + n]);
}

// ---------------------------------------------------------------------------
// fp16 GEMM: C[M,Ntot] = A[M,K] @ Bt[Ntot,K]^T (+bias)
// CTA tile 64x128, 8 warps (warp tile 32x32), BK=64, 2-stage cp.async,
// 3 CTAs/SM (24 warps) for latency hiding. K-major B, non-trans ldmatrix.
// ---------------------------------------------------------------------------
#define BM 64
#define BN 128
#define BK 64
#define TS 72
#define A_STAGE (BM * TS)                 // 4608 halfs
#define B_STAGE (BN * TS)                 // 9216 halfs
#define STAGE_H (A_STAGE + B_STAGE)       // 13824 halfs = 27648 B
#define GSMEM (2 * STAGE_H * 2)           // 55296 bytes

template<bool HALF_OUT>
__global__ void __launch_bounds__(256, 3) gemm_f16(
    const __half* __restrict__ A, const __half* __restrict__ Bt,
    const float* __restrict__ bias, void* __restrict__ Cout,
    int Ntot, int K)
{
    extern __shared__ __half sh[];

    const int tid  = threadIdx.x;
    const int lane = tid & 31;
    const int wid  = tid >> 5;
    const int g    = lane >> 2;
    const int tg   = lane & 3;
    const int mBase = blockIdx.y * BM;
    const int nBase = blockIdx.x * BN;
    const int wm = (wid >> 2) * 32;       // 2(M) x 4(N) warps, warp tile 32x32
    const int wn = (wid & 3) * 32;
    const int KC = K >> 6;

    float acc[2][4][4];
    #pragma unroll
    for (int a = 0; a < 2; a++)
        #pragma unroll
        for (int b = 0; b < 4; b++)
            #pragma unroll
            for (int c = 0; c < 4; c++) acc[a][b][c] = 0.f;

    const int fRow = (lane & 7) + ((lane >> 3) & 1) * 8;
    const int fKo  = ((lane >> 4) & 1) * 8;

    auto stage = [&](int kc, int s) {
        const int k0 = kc * BK;
        __half* Ad = sh + s * STAGE_H;
        __half* Bd = Ad + A_STAGE;
        #pragma unroll
        for (int i = 0; i < 2; i++) {            // A: 64 rows x 8 x 16B
            int id = tid + i * 256;
            int r = id >> 3, ch = id & 7;
            const __half* src = A + (size_t)(mBase + r) * K + k0 + ch * 8;
            unsigned dst = (unsigned)__cvta_generic_to_shared(Ad + r * TS + ch * 8);
            asm volatile("cp.async.cg.shared.global [%0], [%1], 16;"
                         :: "r"(dst), "l"(src));
        }
        #pragma unroll
        for (int i = 0; i < 4; i++) {            // B: 128 n-rows x 8 x 16B
            int id = tid + i * 256;
            int r = id >> 3, ch = id & 7;
            const __half* src = Bt + (size_t)(nBase + r) * K + k0 + ch * 8;
            unsigned dst = (unsigned)__cvta_generic_to_shared(Bd + r * TS + ch * 8);
            asm volatile("cp.async.cg.shared.global [%0], [%1], 16;"
                         :: "r"(dst), "l"(src));
        }
        asm volatile("cp.async.commit_group;" ::: "memory");
    };

    stage(0, 0);
    if (KC > 1) stage(1, 1);

    for (int c = 0; c < KC; c++) {
        if (c + 1 < KC) asm volatile("cp.async.wait_group 1;" ::: "memory");
        else            asm volatile("cp.async.wait_group 0;" ::: "memory");
        __syncthreads();

        const int s = c & 1;
        const __half* Ab = sh + s * STAGE_H;
        const __half* Bb = Ab + A_STAGE;

        #pragma unroll
        for (int kk = 0; kk < BK; kk += 16) {
            unsigned a[2][4], b[2][4];
            #pragma unroll
            for (int mi = 0; mi < 2; mi++) {
                unsigned sa = (unsigned)__cvta_generic_to_shared(
                    Ab + (wm + mi * 16 + fRow) * TS + kk + fKo);
                asm volatile(
                    "ldmatrix.sync.aligned.m8n8.x4.shared.b16 {%0,%1,%2,%3},[%4];"
                    : "=r"(a[mi][0]), "=r"(a[mi][1]), "=r"(a[mi][2]), "=r"(a[mi][3])
                    : "r"(sa));
            }
            #pragma unroll
            for (int gb = 0; gb < 2; gb++) {
                unsigned sb = (unsigned)__cvta_generic_to_shared(
                    Bb + (wn + gb * 16 + fRow) * TS + kk + fKo);
                asm volatile(
                    "ldmatrix.sync.aligned.m8n8.x4.shared.b16 {%0,%1,%2,%3},[%4];"
                    : "=r"(b[gb][0]), "=r"(b[gb][1]), "=r"(b[gb][2]), "=r"(b[gb][3])
                    : "r"(sb));
            }
            #pragma unroll
            for (int mi = 0; mi < 2; mi++)
                #pragma unroll
                for (int ni = 0; ni < 4; ni++) {
                    const int gb = ni >> 1, sel = ni & 1;
                    asm volatile(
                        "mma.sync.aligned.m16n8k16.row.col.f32.f16.f16.f32 "
                        "{%0,%1,%2,%3},{%4,%5,%6,%7},{%8,%9},{%0,%1,%2,%3};"
                        : "+f"(acc[mi][ni][0]), "+f"(acc[mi][ni][1]),
                          "+f"(acc[mi][ni][2]), "+f"(acc[mi][ni][3])
                        : "r"(a[mi][0]), "r"(a[mi][1]), "r"(a[mi][2]), "r"(a[mi][3]),
                          "r"(b[gb][sel]), "r"(b[gb][sel + 2]));
                }
        }
        __syncthreads();
        if (c + 2 < KC) stage(c + 2, s);
    }

    // epilogue
    #pragma unroll
    for (int mi = 0; mi < 2; mi++) {
        int r0 = mBase + wm + mi * 16 + g;
        #pragma unroll
        for (int ni = 0; ni < 4; ni++) {
            int c0 = nBase + wn + ni * 8 + 2 * tg;
            if (HALF_OUT) {
                __half* C = (__half*)Cout;
                *(__half2*)(C + (size_t)r0 * Ntot + c0) =
                    __floats2half2_rn(acc[mi][ni][0], acc[mi][ni][1]);
                *(__half2*)(C + (size_t)(r0 + 8) * Ntot + c0) =
                    __floats2half2_rn(acc[mi][ni][2], acc[mi][ni][3]);
            } else {
                float* C = (float*)Cout;
                float b0 = bias[c0], b1 = bias[c0 + 1];
                C[(size_t)r0 * Ntot + c0]           = acc[mi][ni][0] + b0;
                C[(size_t)r0 * Ntot + c0 + 1]       = acc[mi][ni][1] + b1;
                C[(size_t)(r0 + 8) * Ntot + c0]     = acc[mi][ni][2] + b0;
                C[(size_t)(r0 + 8) * Ntot + c0 + 1] = acc[mi][ni][3] + b1;
            }
        }
    }
}

// ---------------------------------------------------------------------------
// MMA-based attention (round-13, unchanged): warp = (block, head).
// ---------------------------------------------------------------------------
#define AT_STRIDE 72
#define AT_MAT    (32 * AT_STRIDE)
#define AT_HEAD   (3 * AT_MAT)
#define ATTN_SMEM (HEADS * AT_HEAD * 2)      // 110592 bytes

__global__ void __launch_bounds__(256, 2) attn_mma(
    const __half* __restrict__ qkv, const float* __restrict__ pos,
    __half* __restrict__ inner)
{
    extern __shared__ __half ash[];
    const int b    = blockIdx.x;
    const int w    = threadIdx.x >> 5;
    const int lane = threadIdx.x & 31;
    const int g    = lane >> 2;
    const int tg   = lane & 3;

    __half* qs = ash + w * AT_HEAD;
    __half* ks = qs + AT_MAT;
    __half* vs = ks + AT_MAT;

    #pragma unroll
    for (int m = 0; m < 3; m++) {
        unsigned* pz = (unsigned*)(qs + m * AT_MAT + 24 * AT_STRIDE);
        for (int i = lane; i < (8 * AT_STRIDE) / 2; i += 32) pz[i] = 0u;
    }
    const __half* gq = qkv + (size_t)b * LINE * QKV + w * DHEAD;
    for (int t = lane; t < 192; t += 32) {
        int r = t >> 3, ch = t & 7;
        size_t off = (size_t)r * QKV + ch * 8;
        *(uint4*)(qs + r * AT_STRIDE + ch * 8) = *(const uint4*)(gq + off);
        *(uint4*)(ks + r * AT_STRIDE + ch * 8) = *(const uint4*)(gq + off + 512);
        *(uint4*)(vs + r * AT_STRIDE + ch * 8) = *(const uint4*)(gq + off + 1024);
    }
    __syncwarp();

    const int fRow = (lane & 7) + ((lane >> 3) & 1) * 8;
    const int fKo  = ((lane >> 4) & 1) * 8;

    float s[2][3][4];
    #pragma unroll
    for (int mi = 0; mi < 2; mi++)
        #pragma unroll
        for (int nt = 0; nt < 3; nt++)
            #pragma unroll
            for (int c = 0; c < 4; c++) s[mi][nt][c] = 0.f;

    #pragma unroll
    for (int kk = 0; kk < 64; kk += 16) {
        unsigned a[2][4], bk[2][4];
        #pragma unroll
        for (int mi = 0; mi < 2; mi++) {
            unsigned sa = (unsigned)__cvta_generic_to_shared(
                qs + (mi * 16 + fRow) * AT_STRIDE + kk + fKo);
            asm volatile(
                "ldmatrix.sync.aligned.m8n8.x4.shared.b16 {%0,%1,%2,%3},[%4];"
                : "=r"(a[mi][0]), "=r"(a[mi][1]), "=r"(a[mi][2]), "=r"(a[mi][3])
                : "r"(sa));
        }
        #pragma unroll
        for (int gb = 0; gb < 2; gb++) {
            unsigned sb = (unsigned)__cvta_generic_to_shared(
                ks + (gb * 16 + fRow) * AT_STRIDE + kk + fKo);
            asm volatile(
                "ldmatrix.sync.aligned.m8n8.x4.shared.b16 {%0,%1,%2,%3},[%4];"
                : "=r"(bk[gb][0]), "=r"(bk[gb][1]), "=r"(bk[gb][2]), "=r"(bk[gb][3])
                : "r"(sb));
        }
        #pragma unroll
        for (int mi = 0; mi < 2; mi++)
            #pragma unroll
            for (int nt = 0; nt < 3; nt++) {
                const int gb = nt >> 1, sel = nt & 1;
                asm volatile(
                    "mma.sync.aligned.m16n8k16.row.col.f32.f16.f16.f32 "
                    "{%0,%1,%2,%3},{%4,%5,%6,%7},{%8,%9},{%0,%1,%2,%3};"
                    : "+f"(s[mi][nt][0]), "+f"(s[mi][nt][1]),
                      "+f"(s[mi][nt][2]), "+f"(s[mi][nt][3])
                    : "r"(a[mi][0]), "r"(a[mi][1]), "r"(a[mi][2]), "r"(a[mi][3]),
                      "r"(bk[gb][sel]), "r"(bk[gb][sel + 2]));
            }
    }

    const float* pb = pos + (size_t)w * LINE * LINE;
    float e[3][6];
    const int rows[3] = {g, g + 8, 16 + g};
    #pragma unroll
    for (int rr = 0; rr < 3; rr++) {
        #pragma unroll
        for (int nt = 0; nt < 3; nt++) {
            float v0, v1;
            if (rr == 0)      { v0 = s[0][nt][0]; v1 = s[0][nt][1]; }
            else if (rr == 1) { v0 = s[0][nt][2]; v1 = s[0][nt][3]; }
            else              { v0 = s[1][nt][0]; v1 = s[1][nt][1]; }
            float2 pe = *(const float2*)(pb + rows[rr] * LINE + nt * 8 + 2 * tg);
            e[rr][2 * nt]     = v0 * 0.125f + pe.x;
            e[rr][2 * nt + 1] = v1 * 0.125f + pe.y;
        }
        float mx = e[rr][0];
        #pragma unroll
        for (int j = 1; j < 6; j++) mx = fmaxf(mx, e[rr][j]);
        mx = fmaxf(mx, __shfl_xor_sync(0xFFFFFFFF, mx, 1));
        mx = fmaxf(mx, __shfl_xor_sync(0xFFFFFFFF, mx, 2));
        float sum = 0.f;
        #pragma unroll
        for (int j = 0; j < 6; j++) { e[rr][j] = __expf(e[rr][j] - mx); sum += e[rr][j]; }
        sum += __shfl_xor_sync(0xFFFFFFFF, sum, 1);
        sum += __shfl_xor_sync(0xFFFFFFFF, sum, 2);
        float inv = 1.f / sum;
        #pragma unroll
        for (int j = 0; j < 6; j++) e[rr][j] *= inv;
    }

    unsigned p[3][3];
    #pragma unroll
    for (int rr = 0; rr < 3; rr++)
        #pragma unroll
        for (int nt = 0; nt < 3; nt++) {
            __half2 h = __floats2half2_rn(e[rr][2 * nt], e[rr][2 * nt + 1]);
            p[rr][nt] = *(unsigned*)&h;
        }
    unsigned Pf[2][2][4];
    Pf[0][0][0] = p[0][0]; Pf[0][0][1] = p[1][0]; Pf[0][0][2] = p[0][1]; Pf[0][0][3] = p[1][1];
    Pf[0][1][0] = p[0][2]; Pf[0][1][1] = p[1][2]; Pf[0][1][2] = 0;       Pf[0][1][3] = 0;
    Pf[1][0][0] = p[2][0]; Pf[1][0][1] = 0;       Pf[1][0][2] = p[2][1]; Pf[1][0][3] = 0;
    Pf[1][1][0] = p[2][2]; Pf[1][1][1] = 0;       Pf[1][1][2] = 0;       Pf[1][1][3] = 0;

    __half* ob = inner + (size_t)(b * LINE) * INNER + w * DHEAD;
    #pragma unroll
    for (int h2 = 0; h2 < 2; h2++) {
        unsigned vb[2][2][4];
        #pragma unroll
        for (int kt = 0; kt < 2; kt++)
            #pragma unroll
            for (int nb = 0; nb < 2; nb++) {
                unsigned sv = (unsigned)__cvta_generic_to_shared(
                    vs + (kt * 16 + fRow) * AT_STRIDE + h2 * 32 + nb * 16 + fKo);
                asm volatile(
                    "ldmatrix.sync.aligned.m8n8.x4.trans.shared.b16 {%0,%1,%2,%3},[%4];"
                    : "=r"(vb[kt][nb][0]), "=r"(vb[kt][nb][1]),
                      "=r"(vb[kt][nb][2]), "=r"(vb[kt][nb][3])
                    : "r"(sv));
            }
        float o[2][4][4];
        #pragma unroll
        for (int mi = 0; mi < 2; mi++)
            #pragma unroll
            for (int n8 = 0; n8 < 4; n8++)
                #pragma unroll
                for (int c = 0; c < 4; c++) o[mi][n8][c] = 0.f;

        #pragma unroll
        for (int mi = 0; mi < 2; mi++)
            #pragma unroll
            for (int n8 = 0; n8 < 4; n8++) {
                const int nb = n8 >> 1, s2 = (n8 & 1) * 2;
                #pragma unroll
                for (int kt = 0; kt < 2; kt++) {
                    asm volatile(
                        "mma.sync.aligned.m16n8k16.row.col.f32.f16.f16.f32 "
                        "{%0,%1,%2,%3},{%4,%5,%6,%7},{%8,%9},{%0,%1,%2,%3};"
                        : "+f"(o[mi][n8][0]), "+f"(o[mi][n8][1]),
                          "+f"(o[mi][n8][2]), "+f"(o[mi][n8][3])
                        : "r"(Pf[mi][kt][0]), "r"(Pf[mi][kt][1]),
                          "r"(Pf[mi][kt][2]), "r"(Pf[mi][kt][3]),
                          "r"(vb[kt][nb][s2]), "r"(vb[kt][nb][s2 + 1]));
                }
            }

        #pragma unroll
        for (int mi = 0; mi < 2; mi++)
            #pragma unroll
            for (int n8 = 0; n8 < 4; n8++) {
                int r0 = mi * 16 + g;
                int c0 = h2 * 32 + n8 * 8 + 2 * tg;
                *(__half2*)(ob + (size_t)r0 * INNER + c0) =
                    __floats2half2_rn(o[mi][n8][0], o[mi][n8][1]);
                if (mi == 0)
                    *(__half2*)(ob + (size_t)(r0 + 8) * INNER + c0) =
                        __floats2half2_rn(o[mi][n8][2], o[mi][n8][3]);
            }
    }
}

// ---------------------------------------------------------------------------
// Launch
// ---------------------------------------------------------------------------
extern "C" void kernel_launch(void* const* d_in, const int* in_sizes, int n_in,
                              void* d_out, int out_size)
{
    (void)in_sizes; (void)n_in; (void)out_size;
    const float* x    = (const float*)d_in[0];
    const float* Wq   = (const float*)d_in[1];
    const float* Wkv  = (const float*)d_in[2];
    const float* Wout = (const float*)d_in[3];
    const float* bout = (const float*)d_in[4];
    const float* pos  = (const float*)d_in[5];
    float* out = (float*)d_out;

    __half *xh, *qkvh, *ih, *wqkvT, *woutT;
    cudaGetSymbolAddress((void**)&xh,    g_xh);
    cudaGetSymbolAddress((void**)&qkvh,  g_qkvh);
    cudaGetSymbolAddress((void**)&ih,    g_ih);
    cudaGetSymbolAddress((void**)&wqkvT, g_wqkvT);
    cudaGetSymbolAddress((void**)&woutT, g_woutT);

    cudaFuncSetAttribute(gemm_f16<true>,
        cudaFuncAttributeMaxDynamicSharedMemorySize, GSMEM);
    cudaFuncSetAttribute(gemm_f16<false>,
        cudaFuncAttributeMaxDynamicSharedMemorySize, GSMEM);
    cudaFuncSetAttribute(attn_mma,
        cudaFuncAttributeMaxDynamicSharedMemorySize, ATTN_SMEM);

    // 0) prep
    f2h_kernel<<<(NROWS * DIM) / 4 / 256, 256>>>(x, xh, NROWS * DIM);
    prep_wqkv<<<QKV, 256>>>(Wq, Wkv, wqkvT);
    prep_wout<<<INNER, 256>>>(Wout, woutT);

    // 1) qkv = x @ [Wq|Wk|Wv]   (fp16 out, ldc = 1536)
    gemm_f16<true><<<dim3(QKV / BN, NROWS / BM), 256, GSMEM>>>(
        xh, wqkvT, nullptr, qkvh, QKV, DIM);

    // 2) attention (tensor-core)
    attn_mma<<<NBLK, 256, ATTN_SMEM>>>(qkvh, pos, ih);

    // 3) out = inner @ Wout + b  (fp32 out)
    gemm_f16<false><<<dim3(DIM / BN, NROWS / BM), 256, GSMEM>>>(
        ih, woutT, bout, out, DIM, INNER);
}

// round 16
// speedup vs baseline: 1.0129x; 1.0129x over previous
#include <cuda_runtime.h>
#include <cuda_fp16.h>

#define DIM    256
#define LINE   24
#define HEADS  8
#define DHEAD  64
#define INNER  512
#define QKV    1536
#define NROWS  196608
#define NBLK   (NROWS / LINE)   // 8192

// ---------------------------------------------------------------------------
// Scratch (device globals, allocation-free)
// ---------------------------------------------------------------------------
__device__ __half g_xh   [(size_t)NROWS * DIM];    // 100 MB
__device__ __half g_qkvh [(size_t)NROWS * QKV];    // 604 MB  (q | k | v)
__device__ __half g_wqkvT[QKV * DIM];              // [n,k] K-major
__device__ __half g_woutT[DIM * INNER];            // [n,k] K-major

// ---------------------------------------------------------------------------
// Prep kernels
// ---------------------------------------------------------------------------
__global__ void __launch_bounds__(256) f2h_kernel(
    const float* __restrict__ in, __half* __restrict__ out, int n)
{
    int i = (blockIdx.x * 256 + threadIdx.x) * 4;
    if (i < n) {
        float4 v = *(const float4*)(in + i);
        *(__half2*)(out + i)     = __floats2half2_rn(v.x, v.y);
        *(__half2*)(out + i + 2) = __floats2half2_rn(v.z, v.w);
    }
}
__global__ void __launch_bounds__(256) prep_wqkv(
    const float* __restrict__ Wq, const float* __restrict__ Wkv,
    __half* __restrict__ wT)
{
    int idx = blockIdx.x * 256 + threadIdx.x;     // 1536*256
    int n = idx >> 8, k = idx & 255;
    float v = (n < 512) ? Wq[(size_t)k * 512 + n]
                        : Wkv[(size_t)k * 1024 + (n - 512)];
    wT[idx] = __float2half_rn(v);
}
__global__ void __launch_bounds__(256) prep_wout(
    const float* __restrict__ Wout, __half* __restrict__ wT)
{
    int idx = blockIdx.x * 256 + threadIdx.x;     // 256*512
    int n = idx >> 9, k = idx & 511;
    wT[idx] = __float2half_rn(Wout[(size_t)k * 256 + n]);
}

// ---------------------------------------------------------------------------
// fp16 GEMM (round-13 config: best measured 636us). CTA 128x128, 8 warps
// (64x32), BK=64, 3-stage cp.async, K-major B, non-trans ldmatrix.
// ---------------------------------------------------------------------------
#define BM 128
#define BN 128
#define BK 64
#define TS 72
#define STAGE_H (BM * TS)
#define GSMEM (3 * 2 * STAGE_H * 2)

__global__ void __launch_bounds__(256) gemm_f16(
    const __half* __restrict__ A, const __half* __restrict__ Bt,
    __half* __restrict__ Cout, int Ntot, int K)
{
    extern __shared__ __half sh[];
    __half* As = sh;
    __half* Bs = sh + 3 * STAGE_H;

    const int tid  = threadIdx.x;
    const int lane = tid & 31;
    const int wid  = tid >> 5;
    const int g    = lane >> 2;
    const int tg   = lane & 3;
    const int mBase = blockIdx.y * BM;
    const int nBase = blockIdx.x * BN;
    const int wm = (wid >> 2) * 64;
    const int wn = (wid & 3) * 32;
    const int KC = K >> 6;

    float acc[4][4][4];
    #pragma unroll
    for (int a = 0; a < 4; a++)
        #pragma unroll
        for (int b = 0; b < 4; b++)
            #pragma unroll
            for (int c = 0; c < 4; c++) acc[a][b][c] = 0.f;

    const int fRow = (lane & 7) + ((lane >> 3) & 1) * 8;
    const int fKo  = ((lane >> 4) & 1) * 8;

    auto stage = [&](int kc, int s) {
        const int k0 = kc * BK;
        __half* Ad = As + s * STAGE_H;
        __half* Bd = Bs + s * STAGE_H;
        #pragma unroll
        for (int i = 0; i < 4; i++) {
            int id = tid + i * 256;
            int r = id >> 3, ch = id & 7;
            const __half* src = A + (size_t)(mBase + r) * K + k0 + ch * 8;
            unsigned dst = (unsigned)__cvta_generic_to_shared(Ad + r * TS + ch * 8);
            asm volatile("cp.async.cg.shared.global [%0], [%1], 16;"
                         :: "r"(dst), "l"(src));
        }
        #pragma unroll
        for (int i = 0; i < 4; i++) {
            int id = tid + i * 256;
            int r = id >> 3, ch = id & 7;
            const __half* src = Bt + (size_t)(nBase + r) * K + k0 + ch * 8;
            unsigned dst = (unsigned)__cvta_generic_to_shared(Bd + r * TS + ch * 8);
            asm volatile("cp.async.cg.shared.global [%0], [%1], 16;"
                         :: "r"(dst), "l"(src));
        }
        asm volatile("cp.async.commit_group;" ::: "memory");
    };

    stage(0, 0);
    if (KC > 1) stage(1, 1);
    if (KC > 2) stage(2, 2);

    for (int c = 0; c < KC; c++) {
        if (c + 3 <= KC)      asm volatile("cp.async.wait_group 2;" ::: "memory");
        else if (c + 2 == KC) asm volatile("cp.async.wait_group 1;" ::: "memory");
        else                  asm volatile("cp.async.wait_group 0;" ::: "memory");
        __syncthreads();

        const int s = c % 3;
        const __half* Ab = As + s * STAGE_H;
        const __half* Bb = Bs + s * STAGE_H;

        #pragma unroll
        for (int kk = 0; kk < BK; kk += 16) {
            unsigned a[4][4], b[2][4];
            #pragma unroll
            for (int mi = 0; mi < 4; mi++) {
                unsigned sa = (unsigned)__cvta_generic_to_shared(
                    Ab + (wm + mi * 16 + fRow) * TS + kk + fKo);
                asm volatile(
                    "ldmatrix.sync.aligned.m8n8.x4.shared.b16 {%0,%1,%2,%3},[%4];"
                    : "=r"(a[mi][0]), "=r"(a[mi][1]), "=r"(a[mi][2]), "=r"(a[mi][3])
                    : "r"(sa));
            }
            #pragma unroll
            for (int gb = 0; gb < 2; gb++) {
                unsigned sb = (unsigned)__cvta_generic_to_shared(
                    Bb + (wn + gb * 16 + fRow) * TS + kk + fKo);
                asm volatile(
                    "ldmatrix.sync.aligned.m8n8.x4.shared.b16 {%0,%1,%2,%3},[%4];"
                    : "=r"(b[gb][0]), "=r"(b[gb][1]), "=r"(b[gb][2]), "=r"(b[gb][3])
                    : "r"(sb));
            }
            #pragma unroll
            for (int mi = 0; mi < 4; mi++)
                #pragma unroll
                for (int ni = 0; ni < 4; ni++) {
                    const int gb = ni >> 1, sel = ni & 1;
                    asm volatile(
                        "mma.sync.aligned.m16n8k16.row.col.f32.f16.f16.f32 "
                        "{%0,%1,%2,%3},{%4,%5,%6,%7},{%8,%9},{%0,%1,%2,%3};"
                        : "+f"(acc[mi][ni][0]), "+f"(acc[mi][ni][1]),
                          "+f"(acc[mi][ni][2]), "+f"(acc[mi][ni][3])
                        : "r"(a[mi][0]), "r"(a[mi][1]), "r"(a[mi][2]), "r"(a[mi][3]),
                          "r"(b[gb][sel]), "r"(b[gb][sel + 2]));
                }
        }
        __syncthreads();
        if (c + 3 < KC) stage(c + 3, s);
    }

    #pragma unroll
    for (int mi = 0; mi < 4; mi++) {
        int r0 = mBase + wm + mi * 16 + g;
        #pragma unroll
        for (int ni = 0; ni < 4; ni++) {
            int c0 = nBase + wn + ni * 8 + 2 * tg;
            *(__half2*)(Cout + (size_t)r0 * Ntot + c0) =
                __floats2half2_rn(acc[mi][ni][0], acc[mi][ni][1]);
            *(__half2*)(Cout + (size_t)(r0 + 8) * Ntot + c0) =
                __floats2half2_rn(acc[mi][ni][2], acc[mi][ni][3]);
        }
    }
}

// ---------------------------------------------------------------------------
// Fused attention + out-projection. CTA = line-block.
// Phase 1 (R13 attention): warp = head, O kept in regs/smem.
// Phase 2: out[24,256] = inner_s[24,512] @ WoutT^T + bias, 8 warps x N=32.
// ---------------------------------------------------------------------------
#define AT_STRIDE 72
#define AT_MAT    (32 * AT_STRIDE)
#define AT_HEAD   (3 * AT_MAT)
#define IS_ST     520                       // inner_s row stride (halfs)
#define WB_OFF    (32 * IS_ST)              // 16640 halfs
#define WB_H      (256 * 72)                // 18432 halfs per buffer
#define FUSE_SMEM (HEADS * AT_HEAD * 2)     // 110592 B (covers both phases)

__global__ void __launch_bounds__(256, 2) attn_out(
    const __half* __restrict__ qkv, const float* __restrict__ pos,
    const __half* __restrict__ Wt, const float* __restrict__ bias,
    float* __restrict__ out)
{
    extern __shared__ __half ash[];
    const int b    = blockIdx.x;
    const int tid  = threadIdx.x;
    const int w    = tid >> 5;
    const int lane = tid & 31;
    const int g    = lane >> 2;
    const int tg   = lane & 3;

    __half* qs = ash + w * AT_HEAD;
    __half* ks = qs + AT_MAT;
    __half* vs = ks + AT_MAT;

    // zero pad rows 24..31 (V pad MUST be 0: P zero-cols x NaN hazard)
    #pragma unroll
    for (int m = 0; m < 3; m++) {
        unsigned* pz = (unsigned*)(qs + m * AT_MAT + 24 * AT_STRIDE);
        for (int i = lane; i < (8 * AT_STRIDE) / 2; i += 32) pz[i] = 0u;
    }
    const __half* gq = qkv + (size_t)b * LINE * QKV + w * DHEAD;
    for (int t = lane; t < 192; t += 32) {
        int r = t >> 3, ch = t & 7;
        size_t off = (size_t)r * QKV + ch * 8;
        *(uint4*)(qs + r * AT_STRIDE + ch * 8) = *(const uint4*)(gq + off);
        *(uint4*)(ks + r * AT_STRIDE + ch * 8) = *(const uint4*)(gq + off + 512);
        *(uint4*)(vs + r * AT_STRIDE + ch * 8) = *(const uint4*)(gq + off + 1024);
    }
    __syncwarp();

    const int fRow = (lane & 7) + ((lane >> 3) & 1) * 8;
    const int fKo  = ((lane >> 4) & 1) * 8;

    // ---- S = Q @ K^T
    float s[2][3][4];
    #pragma unroll
    for (int mi = 0; mi < 2; mi++)
        #pragma unroll
        for (int nt = 0; nt < 3; nt++)
            #pragma unroll
            for (int c = 0; c < 4; c++) s[mi][nt][c] = 0.f;

    #pragma unroll
    for (int kk = 0; kk < 64; kk += 16) {
        unsigned a[2][4], bk[2][4];
        #pragma unroll
        for (int mi = 0; mi < 2; mi++) {
            unsigned sa = (unsigned)__cvta_generic_to_shared(
                qs + (mi * 16 + fRow) * AT_STRIDE + kk + fKo);
            asm volatile(
                "ldmatrix.sync.aligned.m8n8.x4.shared.b16 {%0,%1,%2,%3},[%4];"
                : "=r"(a[mi][0]), "=r"(a[mi][1]), "=r"(a[mi][2]), "=r"(a[mi][3])
                : "r"(sa));
        }
        #pragma unroll
        for (int gb = 0; gb < 2; gb++) {
            unsigned sb = (unsigned)__cvta_generic_to_shared(
                ks + (gb * 16 + fRow) * AT_STRIDE + kk + fKo);
            asm volatile(
                "ldmatrix.sync.aligned.m8n8.x4.shared.b16 {%0,%1,%2,%3},[%4];"
                : "=r"(bk[gb][0]), "=r"(bk[gb][1]), "=r"(bk[gb][2]), "=r"(bk[gb][3])
                : "r"(sb));
        }
        #pragma unroll
        for (int mi = 0; mi < 2; mi++)
            #pragma unroll
            for (int nt = 0; nt < 3; nt++) {
                const int gb = nt >> 1, sel = nt & 1;
                asm volatile(
                    "mma.sync.aligned.m16n8k16.row.col.f32.f16.f16.f32 "
                    "{%0,%1,%2,%3},{%4,%5,%6,%7},{%8,%9},{%0,%1,%2,%3};"
                    : "+f"(s[mi][nt][0]), "+f"(s[mi][nt][1]),
                      "+f"(s[mi][nt][2]), "+f"(s[mi][nt][3])
                    : "r"(a[mi][0]), "r"(a[mi][1]), "r"(a[mi][2]), "r"(a[mi][3]),
                      "r"(bk[gb][sel]), "r"(bk[gb][sel + 2]));
            }
    }

    // ---- softmax (rows g, g+8, 16+g)
    const float* pb = pos + (size_t)w * LINE * LINE;
    float e[3][6];
    const int rows[3] = {g, g + 8, 16 + g};
    #pragma unroll
    for (int rr = 0; rr < 3; rr++) {
        #pragma unroll
        for (int nt = 0; nt < 3; nt++) {
            float v0, v1;
            if (rr == 0)      { v0 = s[0][nt][0]; v1 = s[0][nt][1]; }
            else if (rr == 1) { v0 = s[0][nt][2]; v1 = s[0][nt][3]; }
            else              { v0 = s[1][nt][0]; v1 = s[1][nt][1]; }
            float2 pe = *(const float2*)(pb + rows[rr] * LINE + nt * 8 + 2 * tg);
            e[rr][2 * nt]     = v0 * 0.125f + pe.x;
            e[rr][2 * nt + 1] = v1 * 0.125f + pe.y;
        }
        float mx = e[rr][0];
        #pragma unroll
        for (int j = 1; j < 6; j++) mx = fmaxf(mx, e[rr][j]);
        mx = fmaxf(mx, __shfl_xor_sync(0xFFFFFFFF, mx, 1));
        mx = fmaxf(mx, __shfl_xor_sync(0xFFFFFFFF, mx, 2));
        float sum = 0.f;
        #pragma unroll
        for (int j = 0; j < 6; j++) { e[rr][j] = __expf(e[rr][j] - mx); sum += e[rr][j]; }
        sum += __shfl_xor_sync(0xFFFFFFFF, sum, 1);
        sum += __shfl_xor_sync(0xFFFFFFFF, sum, 2);
        float inv = 1.f / sum;
        #pragma unroll
        for (int j = 0; j < 6; j++) e[rr][j] *= inv;
    }

    unsigned p[3][3];
    #pragma unroll
    for (int rr = 0; rr < 3; rr++)
        #pragma unroll
        for (int nt = 0; nt < 3; nt++) {
            __half2 h = __floats2half2_rn(e[rr][2 * nt], e[rr][2 * nt + 1]);
            p[rr][nt] = *(unsigned*)&h;
        }
    unsigned Pf[2][2][4];
    Pf[0][0][0] = p[0][0]; Pf[0][0][1] = p[1][0]; Pf[0][0][2] = p[0][1]; Pf[0][0][3] = p[1][1];
    Pf[0][1][0] = p[0][2]; Pf[0][1][1] = p[1][2]; Pf[0][1][2] = 0;       Pf[0][1][3] = 0;
    Pf[1][0][0] = p[2][0]; Pf[1][0][1] = 0;       Pf[1][0][2] = p[2][1]; Pf[1][0][3] = 0;
    Pf[1][1][0] = p[2][2]; Pf[1][1][1] = 0;       Pf[1][1][2] = 0;       Pf[1][1][3] = 0;

    // ---- hoist all V fragments to registers (frees smem at the barrier)
    unsigned vb[2][2][2][4];   // [h2][kt][nb][4]
    #pragma unroll
    for (int h2 = 0; h2 < 2; h2++)
        #pragma unroll
        for (int kt = 0; kt < 2; kt++)
            #pragma unroll
            for (int nb = 0; nb < 2; nb++) {
                unsigned sv = (unsigned)__cvta_generic_to_shared(
                    vs + (kt * 16 + fRow) * AT_STRIDE + h2 * 32 + nb * 16 + fKo);
                asm volatile(
                    "ldmatrix.sync.aligned.m8n8.x4.trans.shared.b16 {%0,%1,%2,%3},[%4];"
                    : "=r"(vb[h2][kt][nb][0]), "=r"(vb[h2][kt][nb][1]),
                      "=r"(vb[h2][kt][nb][2]), "=r"(vb[h2][kt][nb][3])
                    : "r"(sv));
            }

    __syncthreads();   // everything needed from phase-1 smem is now in registers

    // ---- O = P @ V  -> inner_s ; also kick off Wout staging
    __half* insm = ash;
    #pragma unroll
    for (int h2 = 0; h2 < 2; h2++) {
        float o[2][4][4];
        #pragma unroll
        for (int mi = 0; mi < 2; mi++)
            #pragma unroll
            for (int n8 = 0; n8 < 4; n8++)
                #pragma unroll
                for (int c = 0; c < 4; c++) o[mi][n8][c] = 0.f;
        #pragma unroll
        for (int mi = 0; mi < 2; mi++)
            #pragma unroll
            for (int n8 = 0; n8 < 4; n8++) {
                const int nb = n8 >> 1, s2 = (n8 & 1) * 2;
                #pragma unroll
                for (int kt = 0; kt < 2; kt++) {
                    asm volatile(
                        "mma.sync.aligned.m16n8k16.row.col.f32.f16.f16.f32 "
                        "{%0,%1,%2,%3},{%4,%5,%6,%7},{%8,%9},{%0,%1,%2,%3};"
                        : "+f"(o[mi][n8][0]), "+f"(o[mi][n8][1]),
                          "+f"(o[mi][n8][2]), "+f"(o[mi][n8][3])
                        : "r"(Pf[mi][kt][0]), "r"(Pf[mi][kt][1]),
                          "r"(Pf[mi][kt][2]), "r"(Pf[mi][kt][3]),
                          "r"(vb[h2][kt][nb][s2]), "r"(vb[h2][kt][nb][s2 + 1]));
                }
            }
        #pragma unroll
        for (int mi = 0; mi < 2; mi++)
            #pragma unroll
            for (int n8 = 0; n8 < 4; n8++) {
                int c = w * 64 + h2 * 32 + n8 * 8 + 2 * tg;
                *(__half2*)(insm + (mi * 16 + g) * IS_ST + c) =
                    __floats2half2_rn(o[mi][n8][0], o[mi][n8][1]);
                if (mi == 0)
                    *(__half2*)(insm + (g + 8) * IS_ST + c) =
                        __floats2half2_rn(o[mi][n8][2], o[mi][n8][3]);
            }
    }

    // stage Wout chunks 0,1 (region disjoint from inner_s)
    auto stage_w = [&](int kc, int sb) {
        __half* Wd = ash + WB_OFF + sb * WB_H;
        #pragma unroll
        for (int i = 0; i < 8; i++) {
            int id = tid + i * 256;
            int r = id >> 3, ch = id & 7;
            const __half* src = Wt + (size_t)r * 512 + kc * 64 + ch * 8;
            unsigned dst = (unsigned)__cvta_generic_to_shared(Wd + r * 72 + ch * 8);
            asm volatile("cp.async.cg.shared.global [%0], [%1], 16;"
                         :: "r"(dst), "l"(src));
        }
        asm volatile("cp.async.commit_group;" ::: "memory");
    };
    stage_w(0, 0);
    stage_w(1, 1);

    // ---- phase 2: out[24,256] = inner_s @ WoutT^T + bias
    const int wn = w * 32;
    float acc[2][4][4];
    #pragma unroll
    for (int a = 0; a < 2; a++)
        #pragma unroll
        for (int bq = 0; bq < 4; bq++)
            #pragma unroll
            for (int c = 0; c < 4; c++) acc[a][bq][c] = 0.f;

    for (int kc = 0; kc < 8; kc++) {
        if (kc < 7) asm volatile("cp.async.wait_group 1;" ::: "memory");
        else        asm volatile("cp.async.wait_group 0;" ::: "memory");
        __syncthreads();

        const __half* Wb = ash + WB_OFF + (kc & 1) * WB_H;
        #pragma unroll
        for (int kk = 0; kk < 64; kk += 16) {
            unsigned a[2][4], bw[2][4];
            #pragma unroll
            for (int mi = 0; mi < 2; mi++) {
                unsigned sa = (unsigned)__cvta_generic_to_shared(
                    insm + (mi * 16 + fRow) * IS_ST + kc * 64 + kk + fKo);
                asm volatile(
                    "ldmatrix.sync.aligned.m8n8.x4.shared.b16 {%0,%1,%2,%3},[%4];"
                    : "=r"(a[mi][0]), "=r"(a[mi][1]), "=r"(a[mi][2]), "=r"(a[mi][3])
                    : "r"(sa));
            }
            #pragma unroll
            for (int gb = 0; gb < 2; gb++) {
                unsigned sb = (unsigned)__cvta_generic_to_shared(
                    Wb + (wn + gb * 16 + fRow) * 72 + kk + fKo);
                asm volatile(
                    "ldmatrix.sync.aligned.m8n8.x4.shared.b16 {%0,%1,%2,%3},[%4];"
                    : "=r"(bw[gb][0]), "=r"(bw[gb][1]), "=r"(bw[gb][2]), "=r"(bw[gb][3])
                    : "r"(sb));
            }
            #pragma unroll
            for (int mi = 0; mi < 2; mi++)
                #pragma unroll
                for (int ni = 0; ni < 4; ni++) {
                    const int gb = ni >> 1, sel = ni & 1;
                    asm volatile(
                        "mma.sync.aligned.m16n8k16.row.col.f32.f16.f16.f32 "
                        "{%0,%1,%2,%3},{%4,%5,%6,%7},{%8,%9},{%0,%1,%2,%3};"
                        : "+f"(acc[mi][ni][0]), "+f"(acc[mi][ni][1]),
                          "+f"(acc[mi][ni][2]), "+f"(acc[mi][ni][3])
                        : "r"(a[mi][0]), "r"(a[mi][1]), "r"(a[mi][2]), "r"(a[mi][3]),
                          "r"(bw[gb][sel]), "r"(bw[gb][sel + 2]));
                }
        }
        __syncthreads();
        if (kc + 2 < 8) stage_w(kc + 2, kc & 1);
    }

    // epilogue: rows 0..23 only
    #pragma unroll
    for (int mi = 0; mi < 2; mi++) {
        int r0 = mi * 16 + g;
        #pragma unroll
        for (int ni = 0; ni < 4; ni++) {
            int c0 = wn + ni * 8 + 2 * tg;
            float b0 = bias[c0], b1 = bias[c0 + 1];
            float* dst = out + (size_t)(b * LINE + r0) * DIM + c0;
            dst[0] = acc[mi][ni][0] + b0;
            dst[1] = acc[mi][ni][1] + b1;
            if (mi == 0) {
                float* dst2 = out + (size_t)(b * LINE + r0 + 8) * DIM + c0;
                dst2[0] = acc[mi][ni][2] + b0;
                dst2[1] = acc[mi][ni][3] + b1;
            }
        }
    }
}

// ---------------------------------------------------------------------------
// Launch
// ---------------------------------------------------------------------------
extern "C" void kernel_launch(void* const* d_in, const int* in_sizes, int n_in,
                              void* d_out, int out_size)
{
    (void)in_sizes; (void)n_in; (void)out_size;
    const float* x    = (const float*)d_in[0];
    const float* Wq   = (const float*)d_in[1];
    const float* Wkv  = (const float*)d_in[2];
    const float* Wout = (const float*)d_in[3];
    const float* bout = (const float*)d_in[4];
    const float* pos  = (const float*)d_in[5];
    float* out = (float*)d_out;

    __half *xh, *qkvh, *wqkvT, *woutT;
    cudaGetSymbolAddress((void**)&xh,    g_xh);
    cudaGetSymbolAddress((void**)&qkvh,  g_qkvh);
    cudaGetSymbolAddress((void**)&wqkvT, g_wqkvT);
    cudaGetSymbolAddress((void**)&woutT, g_woutT);

    cudaFuncSetAttribute(gemm_f16,
        cudaFuncAttributeMaxDynamicSharedMemorySize, GSMEM);
    cudaFuncSetAttribute(attn_out,
        cudaFuncAttributeMaxDynamicSharedMemorySize, FUSE_SMEM);

    // 0) prep
    f2h_kernel<<<(NROWS * DIM) / 4 / 256, 256>>>(x, xh, NROWS * DIM);
    prep_wqkv<<<QKV, 256>>>(Wq, Wkv, wqkvT);
    prep_wout<<<INNER, 256>>>(Wout, woutT);

    // 1) qkv = x @ [Wq|Wk|Wv]   (fp16 out, ldc = 1536)
    gemm_f16<<<dim3(QKV / BN, NROWS / BM), 256, GSMEM>>>(
        xh, wqkvT, qkvh, QKV, DIM);

    // 2) fused attention + out-projection (writes d_out directly)
    attn_out<<<NBLK, 256, FUSE_SMEM>>>(qkvh, pos, woutT, bout, out);
}

// round 17
// speedup vs baseline: 1.0142x; 1.0013x over previous
#include <cuda_runtime.h>
#include <cuda_fp16.h>

#define DIM    256
#define LINE   24
#define HEADS  8
#define DHEAD  64
#define INNER  512
#define QKV    1536
#define NROWS  196608
#define NBLK   (NROWS / LINE)   // 8192

// ---------------------------------------------------------------------------
// Scratch (device globals, allocation-free)
// ---------------------------------------------------------------------------
__device__ __half g_xh   [(size_t)NROWS * DIM];    // 100 MB
__device__ __half g_qkvh [(size_t)NROWS * QKV];    // 604 MB  (q | k | v)
__device__ __half g_wqkvT[QKV * DIM];              // [n,k] K-major
__device__ __half g_woutT[DIM * INNER];            // [n,k] K-major

// ---------------------------------------------------------------------------
// Prep kernels
// ---------------------------------------------------------------------------
__global__ void __launch_bounds__(256) f2h_kernel(
    const float* __restrict__ in, __half* __restrict__ out, int n)
{
    int i = (blockIdx.x * 256 + threadIdx.x) * 4;
    if (i < n) {
        float4 v = *(const float4*)(in + i);
        *(__half2*)(out + i)     = __floats2half2_rn(v.x, v.y);
        *(__half2*)(out + i + 2) = __floats2half2_rn(v.z, v.w);
    }
}
__global__ void __launch_bounds__(256) prep_wqkv(
    const float* __restrict__ Wq, const float* __restrict__ Wkv,
    __half* __restrict__ wT)
{
    int idx = blockIdx.x * 256 + threadIdx.x;     // 1536*256
    int n = idx >> 8, k = idx & 255;
    float v = (n < 512) ? Wq[(size_t)k * 512 + n]
                        : Wkv[(size_t)k * 1024 + (n - 512)];
    wT[idx] = __float2half_rn(v);
}
__global__ void __launch_bounds__(256) prep_wout(
    const float* __restrict__ Wout, __half* __restrict__ wT)
{
    int idx = blockIdx.x * 256 + threadIdx.x;     // 256*512
    int n = idx >> 9, k = idx & 511;
    wT[idx] = __float2half_rn(Wout[(size_t)k * 256 + n]);
}

// ---------------------------------------------------------------------------
// fp16 GEMM (best measured config). CTA 128x128, 8 warps (64x32), BK=64,
// 3-stage cp.async, K-major B, non-trans ldmatrix.
// ---------------------------------------------------------------------------
#define BM 128
#define BN 128
#define BK 64
#define TS 72
#define STAGE_H (BM * TS)
#define GSMEM (3 * 2 * STAGE_H * 2)

__global__ void __launch_bounds__(256) gemm_f16(
    const __half* __restrict__ A, const __half* __restrict__ Bt,
    __half* __restrict__ Cout, int Ntot, int K)
{
    extern __shared__ __half sh[];
    __half* As = sh;
    __half* Bs = sh + 3 * STAGE_H;

    const int tid  = threadIdx.x;
    const int lane = tid & 31;
    const int wid  = tid >> 5;
    const int g    = lane >> 2;
    const int tg   = lane & 3;
    const int mBase = blockIdx.y * BM;
    const int nBase = blockIdx.x * BN;
    const int wm = (wid >> 2) * 64;
    const int wn = (wid & 3) * 32;
    const int KC = K >> 6;

    float acc[4][4][4];
    #pragma unroll
    for (int a = 0; a < 4; a++)
        #pragma unroll
        for (int b = 0; b < 4; b++)
            #pragma unroll
            for (int c = 0; c < 4; c++) acc[a][b][c] = 0.f;

    const int fRow = (lane & 7) + ((lane >> 3) & 1) * 8;
    const int fKo  = ((lane >> 4) & 1) * 8;

    auto stage = [&](int kc, int s) {
        const int k0 = kc * BK;
        __half* Ad = As + s * STAGE_H;
        __half* Bd = Bs + s * STAGE_H;
        #pragma unroll
        for (int i = 0; i < 4; i++) {
            int id = tid + i * 256;
            int r = id >> 3, ch = id & 7;
            const __half* src = A + (size_t)(mBase + r) * K + k0 + ch * 8;
            unsigned dst = (unsigned)__cvta_generic_to_shared(Ad + r * TS + ch * 8);
            asm volatile("cp.async.cg.shared.global [%0], [%1], 16;"
                         :: "r"(dst), "l"(src));
        }
        #pragma unroll
        for (int i = 0; i < 4; i++) {
            int id = tid + i * 256;
            int r = id >> 3, ch = id & 7;
            const __half* src = Bt + (size_t)(nBase + r) * K + k0 + ch * 8;
            unsigned dst = (unsigned)__cvta_generic_to_shared(Bd + r * TS + ch * 8);
            asm volatile("cp.async.cg.shared.global [%0], [%1], 16;"
                         :: "r"(dst), "l"(src));
        }
        asm volatile("cp.async.commit_group;" ::: "memory");
    };

    stage(0, 0);
    if (KC > 1) stage(1, 1);
    if (KC > 2) stage(2, 2);

    for (int c = 0; c < KC; c++) {
        if (c + 3 <= KC)      asm volatile("cp.async.wait_group 2;" ::: "memory");
        else if (c + 2 == KC) asm volatile("cp.async.wait_group 1;" ::: "memory");
        else                  asm volatile("cp.async.wait_group 0;" ::: "memory");
        __syncthreads();

        const int s = c % 3;
        const __half* Ab = As + s * STAGE_H;
        const __half* Bb = Bs + s * STAGE_H;

        #pragma unroll
        for (int kk = 0; kk < BK; kk += 16) {
            unsigned a[4][4], b[2][4];
            #pragma unroll
            for (int mi = 0; mi < 4; mi++) {
                unsigned sa = (unsigned)__cvta_generic_to_shared(
                    Ab + (wm + mi * 16 + fRow) * TS + kk + fKo);
                asm volatile(
                    "ldmatrix.sync.aligned.m8n8.x4.shared.b16 {%0,%1,%2,%3},[%4];"
                    : "=r"(a[mi][0]), "=r"(a[mi][1]), "=r"(a[mi][2]), "=r"(a[mi][3])
                    : "r"(sa));
            }
            #pragma unroll
            for (int gb = 0; gb < 2; gb++) {
                unsigned sb = (unsigned)__cvta_generic_to_shared(
                    Bb + (wn + gb * 16 + fRow) * TS + kk + fKo);
                asm volatile(
                    "ldmatrix.sync.aligned.m8n8.x4.shared.b16 {%0,%1,%2,%3},[%4];"
                    : "=r"(b[gb][0]), "=r"(b[gb][1]), "=r"(b[gb][2]), "=r"(b[gb][3])
                    : "r"(sb));
            }
            #pragma unroll
            for (int mi = 0; mi < 4; mi++)
                #pragma unroll
                for (int ni = 0; ni < 4; ni++) {
                    const int gb = ni >> 1, sel = ni & 1;
                    asm volatile(
                        "mma.sync.aligned.m16n8k16.row.col.f32.f16.f16.f32 "
                        "{%0,%1,%2,%3},{%4,%5,%6,%7},{%8,%9},{%0,%1,%2,%3};"
                        : "+f"(acc[mi][ni][0]), "+f"(acc[mi][ni][1]),
                          "+f"(acc[mi][ni][2]), "+f"(acc[mi][ni][3])
                        : "r"(a[mi][0]), "r"(a[mi][1]), "r"(a[mi][2]), "r"(a[mi][3]),
                          "r"(b[gb][sel]), "r"(b[gb][sel + 2]));
                }
        }
        __syncthreads();
        if (c + 3 < KC) stage(c + 3, s);
    }

    #pragma unroll
    for (int mi = 0; mi < 4; mi++) {
        int r0 = mBase + wm + mi * 16 + g;
        #pragma unroll
        for (int ni = 0; ni < 4; ni++) {
            int c0 = nBase + wn + ni * 8 + 2 * tg;
            *(__half2*)(Cout + (size_t)r0 * Ntot + c0) =
                __floats2half2_rn(acc[mi][ni][0], acc[mi][ni][1]);
            *(__half2*)(Cout + (size_t)(r0 + 8) * Ntot + c0) =
                __floats2half2_rn(acc[mi][ni][2], acc[mi][ni][3]);
        }
    }
}

// ---------------------------------------------------------------------------
// Fused attention + out-projection, 2 line-blocks per CTA (512 threads).
// Phase 1: warp = (local block, head), R13 attention; O packed in regs.
// Phase 2: out[48,256] = inner_s[48,512] @ WoutT^T + bias; warp tile 48x16
//          -> 100% M-utilization (48 = 3 x 16).
// ---------------------------------------------------------------------------
#define AT_STRIDE 72
#define AT_MAT    (32 * AT_STRIDE)
#define AT_HEAD   (3 * AT_MAT)               // 6912 halfs / unit
#define IS_ST     520                        // inner_s row stride (halfs)
#define WB_OFF    (48 * IS_ST)               // 24960 halfs
#define WB_H      (256 * 72)                 // 18432 halfs / buffer
#define FUSE_SMEM (16 * AT_HEAD * 2)         // 221184 bytes

__global__ void __launch_bounds__(512, 1) attn_out(
    const __half* __restrict__ qkv, const float* __restrict__ pos,
    const __half* __restrict__ Wt, const float* __restrict__ bias,
    float* __restrict__ out)
{
    extern __shared__ __half ash[];
    const int b    = blockIdx.x;             // pair of line-blocks
    const int tid  = threadIdx.x;
    const int u    = tid >> 5;               // unit 0..15
    const int lane = tid & 31;
    const int g    = lane >> 2;
    const int tg   = lane & 3;
    const int blkL = u >> 3;                 // local block 0/1
    const int hd   = u & 7;                  // head

    __half* qs = ash + u * AT_HEAD;
    __half* ks = qs + AT_MAT;
    __half* vs = ks + AT_MAT;

    // zero pad rows 24..31 (V pad MUST be 0)
    #pragma unroll
    for (int m = 0; m < 3; m++) {
        unsigned* pz = (unsigned*)(qs + m * AT_MAT + 24 * AT_STRIDE);
        for (int i = lane; i < (8 * AT_STRIDE) / 2; i += 32) pz[i] = 0u;
    }
    const __half* gq = qkv + ((size_t)b * 48 + blkL * 24) * QKV + hd * DHEAD;
    for (int t = lane; t < 192; t += 32) {
        int r = t >> 3, ch = t & 7;
        size_t off = (size_t)r * QKV + ch * 8;
        *(uint4*)(qs + r * AT_STRIDE + ch * 8) = *(const uint4*)(gq + off);
        *(uint4*)(ks + r * AT_STRIDE + ch * 8) = *(const uint4*)(gq + off + 512);
        *(uint4*)(vs + r * AT_STRIDE + ch * 8) = *(const uint4*)(gq + off + 1024);
    }
    __syncwarp();

    const int fRow = (lane & 7) + ((lane >> 3) & 1) * 8;
    const int fKo  = ((lane >> 4) & 1) * 8;

    // ---- S = Q @ K^T
    float s[2][3][4];
    #pragma unroll
    for (int mi = 0; mi < 2; mi++)
        #pragma unroll
        for (int nt = 0; nt < 3; nt++)
            #pragma unroll
            for (int c = 0; c < 4; c++) s[mi][nt][c] = 0.f;

    #pragma unroll
    for (int kk = 0; kk < 64; kk += 16) {
        unsigned a[2][4], bk[2][4];
        #pragma unroll
        for (int mi = 0; mi < 2; mi++) {
            unsigned sa = (unsigned)__cvta_generic_to_shared(
                qs + (mi * 16 + fRow) * AT_STRIDE + kk + fKo);
            asm volatile(
                "ldmatrix.sync.aligned.m8n8.x4.shared.b16 {%0,%1,%2,%3},[%4];"
                : "=r"(a[mi][0]), "=r"(a[mi][1]), "=r"(a[mi][2]), "=r"(a[mi][3])
                : "r"(sa));
        }
        #pragma unroll
        for (int gb = 0; gb < 2; gb++) {
            unsigned sb = (unsigned)__cvta_generic_to_shared(
                ks + (gb * 16 + fRow) * AT_STRIDE + kk + fKo);
            asm volatile(
                "ldmatrix.sync.aligned.m8n8.x4.shared.b16 {%0,%1,%2,%3},[%4];"
                : "=r"(bk[gb][0]), "=r"(bk[gb][1]), "=r"(bk[gb][2]), "=r"(bk[gb][3])
                : "r"(sb));
        }
        #pragma unroll
        for (int mi = 0; mi < 2; mi++)
            #pragma unroll
            for (int nt = 0; nt < 3; nt++) {
                const int gb = nt >> 1, sel = nt & 1;
                asm volatile(
                    "mma.sync.aligned.m16n8k16.row.col.f32.f16.f16.f32 "
                    "{%0,%1,%2,%3},{%4,%5,%6,%7},{%8,%9},{%0,%1,%2,%3};"
                    : "+f"(s[mi][nt][0]), "+f"(s[mi][nt][1]),
                      "+f"(s[mi][nt][2]), "+f"(s[mi][nt][3])
                    : "r"(a[mi][0]), "r"(a[mi][1]), "r"(a[mi][2]), "r"(a[mi][3]),
                      "r"(bk[gb][sel]), "r"(bk[gb][sel + 2]));
            }
    }

    // ---- softmax (rows g, g+8, 16+g)
    const float* pb = pos + (size_t)hd * LINE * LINE;
    float e[3][6];
    const int rows[3] = {g, g + 8, 16 + g};
    #pragma unroll
    for (int rr = 0; rr < 3; rr++) {
        #pragma unroll
        for (int nt = 0; nt < 3; nt++) {
            float v0, v1;
            if (rr == 0)      { v0 = s[0][nt][0]; v1 = s[0][nt][1]; }
            else if (rr == 1) { v0 = s[0][nt][2]; v1 = s[0][nt][3]; }
            else              { v0 = s[1][nt][0]; v1 = s[1][nt][1]; }
            float2 pe = *(const float2*)(pb + rows[rr] * LINE + nt * 8 + 2 * tg);
            e[rr][2 * nt]     = v0 * 0.125f + pe.x;
            e[rr][2 * nt + 1] = v1 * 0.125f + pe.y;
        }
        float mx = e[rr][0];
        #pragma unroll
        for (int j = 1; j < 6; j++) mx = fmaxf(mx, e[rr][j]);
        mx = fmaxf(mx, __shfl_xor_sync(0xFFFFFFFF, mx, 1));
        mx = fmaxf(mx, __shfl_xor_sync(0xFFFFFFFF, mx, 2));
        float sum = 0.f;
        #pragma unroll
        for (int j = 0; j < 6; j++) { e[rr][j] = __expf(e[rr][j] - mx); sum += e[rr][j]; }
        sum += __shfl_xor_sync(0xFFFFFFFF, sum, 1);
        sum += __shfl_xor_sync(0xFFFFFFFF, sum, 2);
        float inv = 1.f / sum;
        #pragma unroll
        for (int j = 0; j < 6; j++) e[rr][j] *= inv;
    }

    unsigned p[3][3];
    #pragma unroll
    for (int rr = 0; rr < 3; rr++)
        #pragma unroll
        for (int nt = 0; nt < 3; nt++) {
            __half2 h = __floats2half2_rn(e[rr][2 * nt], e[rr][2 * nt + 1]);
            p[rr][nt] = *(unsigned*)&h;
        }
    unsigned Pf[2][2][4];
    Pf[0][0][0] = p[0][0]; Pf[0][0][1] = p[1][0]; Pf[0][0][2] = p[0][1]; Pf[0][0][3] = p[1][1];
    Pf[0][1][0] = p[0][2]; Pf[0][1][1] = p[1][2]; Pf[0][1][2] = 0;       Pf[0][1][3] = 0;
    Pf[1][0][0] = p[2][0]; Pf[1][0][1] = 0;       Pf[1][0][2] = p[2][1]; Pf[1][0][3] = 0;
    Pf[1][1][0] = p[2][2]; Pf[1][1][1] = 0;       Pf[1][1][2] = 0;       Pf[1][1][3] = 0;

    // ---- O = P @ V  (V from smem, pre-barrier); pack O into registers
    unsigned oh[2][12];   // [h2][n8*3 + {r_g, r_g8, r_16g}]
    #pragma unroll
    for (int h2 = 0; h2 < 2; h2++) {
        unsigned vb[2][2][4];
        #pragma unroll
        for (int kt = 0; kt < 2; kt++)
            #pragma unroll
            for (int nb = 0; nb < 2; nb++) {
                unsigned sv = (unsigned)__cvta_generic_to_shared(
                    vs + (kt * 16 + fRow) * AT_STRIDE + h2 * 32 + nb * 16 + fKo);
                asm volatile(
                    "ldmatrix.sync.aligned.m8n8.x4.trans.shared.b16 {%0,%1,%2,%3},[%4];"
                    : "=r"(vb[kt][nb][0]), "=r"(vb[kt][nb][1]),
                      "=r"(vb[kt][nb][2]), "=r"(vb[kt][nb][3])
                    : "r"(sv));
            }
        float o[2][4][4];
        #pragma unroll
        for (int mi = 0; mi < 2; mi++)
            #pragma unroll
            for (int n8 = 0; n8 < 4; n8++)
                #pragma unroll
                for (int c = 0; c < 4; c++) o[mi][n8][c] = 0.f;
        #pragma unroll
        for (int mi = 0; mi < 2; mi++)
            #pragma unroll
            for (int n8 = 0; n8 < 4; n8++) {
                const int nb = n8 >> 1, s2 = (n8 & 1) * 2;
                #pragma unroll
                for (int kt = 0; kt < 2; kt++) {
                    asm volatile(
                        "mma.sync.aligned.m16n8k16.row.col.f32.f16.f16.f32 "
                        "{%0,%1,%2,%3},{%4,%5,%6,%7},{%8,%9},{%0,%1,%2,%3};"
                        : "+f"(o[mi][n8][0]), "+f"(o[mi][n8][1]),
                          "+f"(o[mi][n8][2]), "+f"(o[mi][n8][3])
                        : "r"(Pf[mi][kt][0]), "r"(Pf[mi][kt][1]),
                          "r"(Pf[mi][kt][2]), "r"(Pf[mi][kt][3]),
                          "r"(vb[kt][nb][s2]), "r"(vb[kt][nb][s2 + 1]));
                }
            }
        #pragma unroll
        for (int n8 = 0; n8 < 4; n8++) {
            __half2 h0 = __floats2half2_rn(o[0][n8][0], o[0][n8][1]); // row g
            __half2 h1 = __floats2half2_rn(o[0][n8][2], o[0][n8][3]); // row g+8
            __half2 h2r = __floats2half2_rn(o[1][n8][0], o[1][n8][1]); // row 16+g
            oh[h2][n8 * 3 + 0] = *(unsigned*)&h0;
            oh[h2][n8 * 3 + 1] = *(unsigned*)&h1;
            oh[h2][n8 * 3 + 2] = *(unsigned*)&h2r;
        }
    }

    __syncthreads();   // all phase-1 smem reads complete chip... CTA-wide

    // ---- write O to inner_s [48 x 512] and start Wout staging
    __half* insm = ash;
    #pragma unroll
    for (int h2 = 0; h2 < 2; h2++)
        #pragma unroll
        for (int n8 = 0; n8 < 4; n8++) {
            int c = hd * 64 + h2 * 32 + n8 * 8 + 2 * tg;
            int rb = blkL * 24;
            *(__half2*)(insm + (rb + g)      * IS_ST + c) = *(__half2*)&oh[h2][n8*3+0];
            *(__half2*)(insm + (rb + g + 8)  * IS_ST + c) = *(__half2*)&oh[h2][n8*3+1];
            *(__half2*)(insm + (rb + 16 + g) * IS_ST + c) = *(__half2*)&oh[h2][n8*3+2];
        }

    auto stage_w = [&](int kc, int sb) {
        __half* Wd = ash + WB_OFF + sb * WB_H;
        #pragma unroll
        for (int i = 0; i < 4; i++) {
            int id = tid + i * 512;
            int r = id >> 3, ch = id & 7;
            const __half* src = Wt + (size_t)r * 512 + kc * 64 + ch * 8;
            unsigned dst = (unsigned)__cvta_generic_to_shared(Wd + r * 72 + ch * 8);
            asm volatile("cp.async.cg.shared.global [%0], [%1], 16;"
                         :: "r"(dst), "l"(src));
        }
        asm volatile("cp.async.commit_group;" ::: "memory");
    };
    stage_w(0, 0);
    stage_w(1, 1);

    // ---- phase 2: out[48,256] = inner_s @ WoutT^T + bias, warp tile 48x16
    const int wn = u * 16;
    float acc[3][2][4];
    #pragma unroll
    for (int a = 0; a < 3; a++)
        #pragma unroll
        for (int bq = 0; bq < 2; bq++)
            #pragma unroll
            for (int c = 0; c < 4; c++) acc[a][bq][c] = 0.f;

    for (int kc = 0; kc < 8; kc++) {
        if (kc < 7) asm volatile("cp.async.wait_group 1;" ::: "memory");
        else        asm volatile("cp.async.wait_group 0;" ::: "memory");
        __syncthreads();

        const __half* Wb = ash + WB_OFF + (kc & 1) * WB_H;
        #pragma unroll
        for (int kk = 0; kk < 64; kk += 16) {
            unsigned a[3][4], bw[4];
            #pragma unroll
            for (int mi = 0; mi < 3; mi++) {
                unsigned sa = (unsigned)__cvta_generic_to_shared(
                    insm + (mi * 16 + fRow) * IS_ST + kc * 64 + kk + fKo);
                asm volatile(
                    "ldmatrix.sync.aligned.m8n8.x4.shared.b16 {%0,%1,%2,%3},[%4];"
                    : "=r"(a[mi][0]), "=r"(a[mi][1]), "=r"(a[mi][2]), "=r"(a[mi][3])
                    : "r"(sa));
            }
            {
                unsigned sb = (unsigned)__cvta_generic_to_shared(
                    Wb + (wn + fRow) * 72 + kk + fKo);
                asm volatile(
                    "ldmatrix.sync.aligned.m8n8.x4.shared.b16 {%0,%1,%2,%3},[%4];"
                    : "=r"(bw[0]), "=r"(bw[1]), "=r"(bw[2]), "=r"(bw[3])
                    : "r"(sb));
            }
            #pragma unroll
            for (int mi = 0; mi < 3; mi++)
                #pragma unroll
                for (int ni = 0; ni < 2; ni++) {
                    asm volatile(
                        "mma.sync.aligned.m16n8k16.row.col.f32.f16.f16.f32 "
                        "{%0,%1,%2,%3},{%4,%5,%6,%7},{%8,%9},{%0,%1,%2,%3};"
                        : "+f"(acc[mi][ni][0]), "+f"(acc[mi][ni][1]),
                          "+f"(acc[mi][ni][2]), "+f"(acc[mi][ni][3])
                        : "r"(a[mi][0]), "r"(a[mi][1]), "r"(a[mi][2]), "r"(a[mi][3]),
                          "r"(bw[ni]), "r"(bw[ni + 2]));
                }
        }
        __syncthreads();
        if (kc + 2 < 8) stage_w(kc + 2, kc & 1);
    }

    // epilogue: all 48 rows valid
    #pragma unroll
    for (int mi = 0; mi < 3; mi++) {
        #pragma unroll
        for (int ni = 0; ni < 2; ni++) {
            int c0 = wn + ni * 8 + 2 * tg;
            float b0 = bias[c0], b1 = bias[c0 + 1];
            int r0 = mi * 16 + g;
            float* d0 = out + ((size_t)b * 48 + r0) * DIM + c0;
            d0[0] = acc[mi][ni][0] + b0;
            d0[1] = acc[mi][ni][1] + b1;
            float* d1 = out + ((size_t)b * 48 + r0 + 8) * DIM + c0;
            d1[0] = acc[mi][ni][2] + b0;
            d1[1] = acc[mi][ni][3] + b1;
        }
    }
}

// ---------------------------------------------------------------------------
// Launch
// ---------------------------------------------------------------------------
extern "C" void kernel_launch(void* const* d_in, const int* in_sizes, int n_in,
                              void* d_out, int out_size)
{
    (void)in_sizes; (void)n_in; (void)out_size;
    const float* x    = (const float*)d_in[0];
    const float* Wq   = (const float*)d_in[1];
    const float* Wkv  = (const float*)d_in[2];
    const float* Wout = (const float*)d_in[3];
    const float* bout = (const float*)d_in[4];
    const float* pos  = (const float*)d_in[5];
    float* out = (float*)d_out;

    __half *xh, *qkvh, *wqkvT, *woutT;
    cudaGetSymbolAddress((void**)&xh,    g_xh);
    cudaGetSymbolAddress((void**)&qkvh,  g_qkvh);
    cudaGetSymbolAddress((void**)&wqkvT, g_wqkvT);
    cudaGetSymbolAddress((void**)&woutT, g_woutT);

    cudaFuncSetAttribute(gemm_f16,
        cudaFuncAttributeMaxDynamicSharedMemorySize, GSMEM);
    cudaFuncSetAttribute(attn_out,
        cudaFuncAttributeMaxDynamicSharedMemorySize, FUSE_SMEM);

    // 0) prep
    f2h_kernel<<<(NROWS * DIM) / 4 / 256, 256>>>(x, xh, NROWS * DIM);
    prep_wqkv<<<QKV, 256>>>(Wq, Wkv, wqkvT);
    prep_wout<<<INNER, 256>>>(Wout, woutT);

    // 1) qkv = x @ [Wq|Wk|Wv]   (fp16 out, ldc = 1536)
    gemm_f16<<<dim3(QKV / BN, NROWS / BM), 256, GSMEM>>>(
        xh, wqkvT, qkvh, QKV, DIM);

    // 2) fused attention + out-projection over 2 line-blocks per CTA
    attn_out<<<NBLK / 2, 512, FUSE_SMEM>>>(qkvh, pos, woutT, bout, out);
}